// round 1
// baseline (speedup 1.0000x reference)
#include <cuda_runtime.h>
#include <cuda_bf16.h>
#include <math.h>

// ---------------- problem constants ----------------
#define HH   16        // H
#define HKV  8
#define DD   128       // D
#define TT   2048      // T
#define HID  2048
#define II   8192      // I
#define NREP 2
#define EPSF 1e-6f
#define SCALEF 0.08838834764831845f   // 1/sqrt(128)

// ---------------- scratch (device globals, no allocs) ----------------
__device__ float g_x  [TT * HID];        // x  = hidden_conv^T
__device__ float g_h  [TT * HID];        // rms(x)
__device__ float g_q  [TT * HH  * DD];   // q  [T, H, D]
__device__ float g_k  [TT * HKV * DD];   // k  [T, HKV, D]
__device__ float g_v  [TT * HKV * DD];   // v
__device__ float g_att[TT * HH  * DD];   // attention out [T, H*D]
__device__ float g_hid[TT * HID];        // residual stream
__device__ float g_h2 [TT * HID];        // rms(hidden)
__device__ float g_gu [TT * 2 * II];     // gate_up output
__device__ float g_act[TT * II];         // silu(gate)*up

// ---------------- transpose: src[R][C] -> dst[C][R] ----------------
__global__ void transpose_k(const float* __restrict__ src, float* __restrict__ dst,
                            int R, int C) {
    __shared__ float tile[32][33];
    int r0 = blockIdx.y * 32, c0 = blockIdx.x * 32;
    int tx = threadIdx.x, ty = threadIdx.y;
    #pragma unroll
    for (int i = ty; i < 32; i += 8)
        tile[i][tx] = src[(size_t)(r0 + i) * C + c0 + tx];
    __syncthreads();
    #pragma unroll
    for (int i = ty; i < 32; i += 8)
        dst[(size_t)(c0 + i) * R + r0 + tx] = tile[tx][i];
}

// ---------------- row RMS norm: Y = X * rsqrt(mean(X^2)+eps) * w ----------------
__global__ void rms_rows(const float* __restrict__ X, const float* __restrict__ w,
                         float* __restrict__ Y, int C) {
    int t = blockIdx.x;
    const float4* x4 = (const float4*)(X + (size_t)t * C);
    const float4* w4 = (const float4*)w;
    float4*       y4 = (float4*)(Y + (size_t)t * C);
    int n4 = C >> 2;                       // 512 for C=2048
    float4 v[4];
    float ss = 0.f;
    int cnt = 0;
    for (int i = threadIdx.x; i < n4; i += 256) {
        float4 a = x4[i];
        v[cnt++] = a;
        ss += a.x * a.x + a.y * a.y + a.z * a.z + a.w * a.w;
    }
    // block reduce
    #pragma unroll
    for (int o = 16; o; o >>= 1) ss += __shfl_xor_sync(0xffffffffu, ss, o);
    __shared__ float warpsum[8];
    if ((threadIdx.x & 31) == 0) warpsum[threadIdx.x >> 5] = ss;
    __syncthreads();
    ss = 0.f;
    #pragma unroll
    for (int i = 0; i < 8; i++) ss += warpsum[i];
    float r = rsqrtf(ss / (float)C + EPSF);
    cnt = 0;
    for (int i = threadIdx.x; i < n4; i += 256) {
        float4 a = v[cnt++];
        float4 ww = w4[i];
        float4 o;
        o.x = a.x * r * ww.x; o.y = a.y * r * ww.y;
        o.z = a.z * r * ww.z; o.w = a.w * r * ww.w;
        y4[i] = o;
    }
}

// ---------------- per-head RMS + RoPE (in place) ----------------
// buf layout [T][nh][128]; grid (nh, T), block 128
__global__ void qk_rms_rope(float* __restrict__ buf, const float* __restrict__ w,
                            const float* __restrict__ cosT, const float* __restrict__ sinT) {
    int h = blockIdx.x, t = blockIdx.y, nh = gridDim.x;
    float* row = buf + ((size_t)t * nh + h) * DD;
    int d = threadIdx.x;
    float v = row[d];
    float ss = v * v;
    #pragma unroll
    for (int o = 16; o; o >>= 1) ss += __shfl_xor_sync(0xffffffffu, ss, o);
    __shared__ float wsum[4];
    if ((d & 31) == 0) wsum[d >> 5] = ss;
    __syncthreads();
    ss = wsum[0] + wsum[1] + wsum[2] + wsum[3];
    float r = rsqrtf(ss / 128.f + EPSF);
    float qn = v * r * w[d];
    __shared__ float sh[128];
    sh[d] = qn;
    __syncthreads();
    float rot = (d < 64) ? -sh[d + 64] : sh[d - 64];
    row[d] = qn * cosT[(size_t)t * DD + d] + rot * sinT[(size_t)t * DD + d];
}

// ---------------- SGEMM: C[M,N] = A[M,K] * B[N,K]^T (+ Res) ----------------
// tiles 128x128x16, 256 threads, 8x8 per thread
__global__ __launch_bounds__(256) void gemm_atb(
    const float* __restrict__ A, const float* __restrict__ B,
    const float* __restrict__ Res, float* __restrict__ C,
    int N, int K) {
    __shared__ float As[16][128];
    __shared__ float Bs[16][128];
    int bm = blockIdx.y * 128;
    int bn = blockIdx.x * 128;
    int tid = threadIdx.x;
    int tx = tid & 15, ty = tid >> 4;
    float acc[8][8] = {};
    const float* Ab = A + (size_t)bm * K;
    const float* Bb = B + (size_t)bn * K;
    for (int k0 = 0; k0 < K; k0 += 16) {
        #pragma unroll
        for (int i = 0; i < 2; i++) {
            int idx = tid + i * 256;
            int r = idx >> 2, c4 = (idx & 3) << 2;
            float4 va = *(const float4*)(Ab + (size_t)r * K + k0 + c4);
            As[c4 + 0][r] = va.x; As[c4 + 1][r] = va.y;
            As[c4 + 2][r] = va.z; As[c4 + 3][r] = va.w;
            float4 vb = *(const float4*)(Bb + (size_t)r * K + k0 + c4);
            Bs[c4 + 0][r] = vb.x; Bs[c4 + 1][r] = vb.y;
            Bs[c4 + 2][r] = vb.z; Bs[c4 + 3][r] = vb.w;
        }
        __syncthreads();
        #pragma unroll
        for (int kk = 0; kk < 16; kk++) {
            float a[8], b[8];
            *(float4*)(a)     = *(const float4*)&As[kk][ty * 8];
            *(float4*)(a + 4) = *(const float4*)&As[kk][ty * 8 + 4];
            *(float4*)(b)     = *(const float4*)&Bs[kk][tx * 8];
            *(float4*)(b + 4) = *(const float4*)&Bs[kk][tx * 8 + 4];
            #pragma unroll
            for (int i = 0; i < 8; i++)
                #pragma unroll
                for (int j = 0; j < 8; j++)
                    acc[i][j] += a[i] * b[j];
        }
        __syncthreads();
    }
    #pragma unroll
    for (int i = 0; i < 8; i++) {
        size_t row = (size_t)(bm + ty * 8 + i);
        float* cp = C + row * N + bn + tx * 8;
        #pragma unroll
        for (int j = 0; j < 8; j += 4) {
            float4 o = make_float4(acc[i][j], acc[i][j + 1], acc[i][j + 2], acc[i][j + 3]);
            if (Res) {
                float4 rv = *(const float4*)(Res + row * N + bn + tx * 8 + j);
                o.x += rv.x; o.y += rv.y; o.z += rv.z; o.w += rv.w;
            }
            *(float4*)(cp + j) = o;
        }
    }
}

// ---------------- flash attention (fp32, causal, 64x64 tiles) ----------------
// Q [T,16,128] (pre-scaled on load), K/V [T,8,128]; grid (T/64, H), 256 thr
#define FLASH_SMEM ((64*128 + 128*68 + 64*68) * 4)
__global__ __launch_bounds__(256) void flash_attn(
    const float* __restrict__ Q, const float* __restrict__ Kg,
    const float* __restrict__ Vg, float* __restrict__ O) {
    extern __shared__ float sm[];
    float* Qs = sm;                 // [64][128]
    float* KT = Qs + 64 * 128;      // K as [128][68] ; reused as V [64][132]
    float* Ss = KT + 128 * 68;      // [64][68]
    __shared__ float m_s[64], l_s[64], al_s[64];

    int h  = blockIdx.y;
    int it = blockIdx.x;
    int i0 = it * 64;
    int hk = h >> 1;                // NREP = 2
    int tid = threadIdx.x, tx = tid & 15, ty = tid >> 4;

    for (int idx = tid; idx < 64 * 32; idx += 256) {
        int r = idx >> 5, d4 = (idx & 31) << 2;
        float4 v = *(const float4*)(Q + ((size_t)(i0 + r) * HH + h) * DD + d4);
        v.x *= SCALEF; v.y *= SCALEF; v.z *= SCALEF; v.w *= SCALEF;
        *(float4*)&Qs[r * 128 + d4] = v;
    }
    if (tid < 64) { m_s[tid] = -1e30f; l_s[tid] = 0.f; }

    float acc[4][8] = {};

    for (int kt = 0; kt <= it; kt++) {
        int j0 = kt * 64;
        __syncthreads();   // Qs ready (1st iter) / prev-iter PV done reading KT,Ss
        // K tile, transposed into KT[d][c]
        for (int idx = tid; idx < 64 * 32; idx += 256) {
            int c = idx >> 5, d4 = (idx & 31) << 2;
            float4 v = *(const float4*)(Kg + ((size_t)(j0 + c) * HKV + hk) * DD + d4);
            KT[(d4 + 0) * 68 + c] = v.x;
            KT[(d4 + 1) * 68 + c] = v.y;
            KT[(d4 + 2) * 68 + c] = v.z;
            KT[(d4 + 3) * 68 + c] = v.w;
        }
        __syncthreads();
        // S = Q K^T (4x4 per thread: rows ty*4.., cols tx*4..)
        float s[4][4] = {};
        #pragma unroll 4
        for (int d = 0; d < 128; d++) {
            float4 kv = *(const float4*)&KT[d * 68 + tx * 4];
            float q0 = Qs[(ty * 4 + 0) * 128 + d];
            float q1 = Qs[(ty * 4 + 1) * 128 + d];
            float q2 = Qs[(ty * 4 + 2) * 128 + d];
            float q3 = Qs[(ty * 4 + 3) * 128 + d];
            s[0][0] += q0 * kv.x; s[0][1] += q0 * kv.y; s[0][2] += q0 * kv.z; s[0][3] += q0 * kv.w;
            s[1][0] += q1 * kv.x; s[1][1] += q1 * kv.y; s[1][2] += q1 * kv.z; s[1][3] += q1 * kv.w;
            s[2][0] += q2 * kv.x; s[2][1] += q2 * kv.y; s[2][2] += q2 * kv.z; s[2][3] += q2 * kv.w;
            s[3][0] += q3 * kv.x; s[3][1] += q3 * kv.y; s[3][2] += q3 * kv.z; s[3][3] += q3 * kv.w;
        }
        bool diag = (kt == it);
        #pragma unroll
        for (int i = 0; i < 4; i++)
            #pragma unroll
            for (int j = 0; j < 4; j++) {
                float vv = s[i][j];
                if (diag && (tx * 4 + j > ty * 4 + i)) vv = -1e30f;
                Ss[(ty * 4 + i) * 68 + tx * 4 + j] = vv;
            }
        __syncthreads();
        // V tile into KT region as [c][132]  (K fully consumed above)
        for (int idx = tid; idx < 64 * 32; idx += 256) {
            int c = idx >> 5, d4 = (idx & 31) << 2;
            float4 v = *(const float4*)(Vg + ((size_t)(j0 + c) * HKV + hk) * DD + d4);
            *(float4*)&KT[c * 132 + d4] = v;
        }
        // online softmax, one row per thread (tid<64)
        if (tid < 64) {
            int r = tid;
            float mo = m_s[r];
            float mx = mo;
            #pragma unroll 8
            for (int c = 0; c < 64; c++) mx = fmaxf(mx, Ss[r * 68 + c]);
            float al = __expf(mo - mx);
            float sum = 0.f;
            #pragma unroll 8
            for (int c = 0; c < 64; c++) {
                float p = __expf(Ss[r * 68 + c] - mx);
                Ss[r * 68 + c] = p;
                sum += p;
            }
            m_s[r] = mx;
            al_s[r] = al;
            l_s[r] = l_s[r] * al + sum;
        }
        __syncthreads();
        // rescale + PV (rows ty*4.., cols tx*8..)
        #pragma unroll
        for (int i = 0; i < 4; i++) {
            float a = al_s[ty * 4 + i];
            #pragma unroll
            for (int j = 0; j < 8; j++) acc[i][j] *= a;
        }
        #pragma unroll 2
        for (int c = 0; c < 64; c++) {
            float p0 = Ss[(ty * 4 + 0) * 68 + c];
            float p1 = Ss[(ty * 4 + 1) * 68 + c];
            float p2 = Ss[(ty * 4 + 2) * 68 + c];
            float p3 = Ss[(ty * 4 + 3) * 68 + c];
            float4 v0 = *(const float4*)&KT[c * 132 + tx * 8];
            float4 v1 = *(const float4*)&KT[c * 132 + tx * 8 + 4];
            acc[0][0] += p0 * v0.x; acc[0][1] += p0 * v0.y; acc[0][2] += p0 * v0.z; acc[0][3] += p0 * v0.w;
            acc[0][4] += p0 * v1.x; acc[0][5] += p0 * v1.y; acc[0][6] += p0 * v1.z; acc[0][7] += p0 * v1.w;
            acc[1][0] += p1 * v0.x; acc[1][1] += p1 * v0.y; acc[1][2] += p1 * v0.z; acc[1][3] += p1 * v0.w;
            acc[1][4] += p1 * v1.x; acc[1][5] += p1 * v1.y; acc[1][6] += p1 * v1.z; acc[1][7] += p1 * v1.w;
            acc[2][0] += p2 * v0.x; acc[2][1] += p2 * v0.y; acc[2][2] += p2 * v0.z; acc[2][3] += p2 * v0.w;
            acc[2][4] += p2 * v1.x; acc[2][5] += p2 * v1.y; acc[2][6] += p2 * v1.z; acc[2][7] += p2 * v1.w;
            acc[3][0] += p3 * v0.x; acc[3][1] += p3 * v0.y; acc[3][2] += p3 * v0.z; acc[3][3] += p3 * v0.w;
            acc[3][4] += p3 * v1.x; acc[3][5] += p3 * v1.y; acc[3][6] += p3 * v1.z; acc[3][7] += p3 * v1.w;
        }
    }
    // write out: O[(i0+r)*H*D + h*D + d], normalized
    #pragma unroll
    for (int i = 0; i < 4; i++) {
        int r = ty * 4 + i;
        float inv = 1.f / l_s[r];
        float* op = O + ((size_t)(i0 + r) * HH + h) * DD + tx * 8;
        float4 o0 = make_float4(acc[i][0] * inv, acc[i][1] * inv, acc[i][2] * inv, acc[i][3] * inv);
        float4 o1 = make_float4(acc[i][4] * inv, acc[i][5] * inv, acc[i][6] * inv, acc[i][7] * inv);
        *(float4*)(op)     = o0;
        *(float4*)(op + 4) = o1;
    }
}

// ---------------- silu(gate) * up ----------------
__global__ void silu_mul(const float* __restrict__ gu, float* __restrict__ act) {
    int idx = blockIdx.x * blockDim.x + threadIdx.x;   // over T*I
    int t = idx >> 13;          // / 8192
    int i = idx & 8191;
    float g = gu[(size_t)t * (2 * II) + i];
    float u = gu[(size_t)t * (2 * II) + II + i];
    act[idx] = g / (1.f + __expf(-g)) * u;
}

// ---------------- launch ----------------
extern "C" void kernel_launch(void* const* d_in, const int* in_sizes, int n_in,
                              void* d_out, int out_size) {
    const float* hc    = (const float*)d_in[0];
    const float* cosT  = (const float*)d_in[1];
    const float* sinT  = (const float*)d_in[2];
    const float* wq    = (const float*)d_in[5];
    const float* wk    = (const float*)d_in[6];
    const float* wv    = (const float*)d_in[7];
    const float* wo    = (const float*)d_in[8];
    const float* wgu   = (const float*)d_in[9];
    const float* wd    = (const float*)d_in[10];
    const float* ilnw  = (const float*)d_in[11];
    const float* plnw  = (const float*)d_in[12];
    const float* qnw   = (const float*)d_in[13];
    const float* knw   = (const float*)d_in[14];
    float* out = (float*)d_out;

    float *px, *ph, *pq, *pk, *pv, *patt, *phid, *ph2, *pgu, *pact;
    cudaGetSymbolAddress((void**)&px,   g_x);
    cudaGetSymbolAddress((void**)&ph,   g_h);
    cudaGetSymbolAddress((void**)&pq,   g_q);
    cudaGetSymbolAddress((void**)&pk,   g_k);
    cudaGetSymbolAddress((void**)&pv,   g_v);
    cudaGetSymbolAddress((void**)&patt, g_att);
    cudaGetSymbolAddress((void**)&phid, g_hid);
    cudaGetSymbolAddress((void**)&ph2,  g_h2);
    cudaGetSymbolAddress((void**)&pgu,  g_gu);
    cudaGetSymbolAddress((void**)&pact, g_act);

    cudaFuncSetAttribute(flash_attn, cudaFuncAttributeMaxDynamicSharedMemorySize, FLASH_SMEM);

    dim3 tb(32, 8);

    // 1. x = hidden_conv^T   (hc is [HID][T])
    transpose_k<<<dim3(TT / 32, HID / 32), tb>>>(hc, px, HID, TT);
    // 2. h = rms(x) * input_ln_w
    rms_rows<<<TT, 256>>>(px, ilnw, ph, HID);
    // 3. QKV projections
    gemm_atb<<<dim3(16, 16), 256>>>(ph, wq, nullptr, pq, HH * DD, HID);
    gemm_atb<<<dim3(8, 16),  256>>>(ph, wk, nullptr, pk, HKV * DD, HID);
    gemm_atb<<<dim3(8, 16),  256>>>(ph, wv, nullptr, pv, HKV * DD, HID);
    // 4. q/k head-RMS + rope (in place)
    qk_rms_rope<<<dim3(HH,  TT), 128>>>(pq, qnw, cosT, sinT);
    qk_rms_rope<<<dim3(HKV, TT), 128>>>(pk, knw, cosT, sinT);
    // 5. attention
    flash_attn<<<dim3(TT / 64, HH), 256, FLASH_SMEM>>>(pq, pk, pv, patt);
    // 6. hidden = x + att @ wo^T
    gemm_atb<<<dim3(16, 16), 256>>>(patt, wo, px, phid, HID, HH * DD);
    // 7. h2 = rms(hidden) * post_ln_w
    rms_rows<<<TT, 256>>>(phid, plnw, ph2, HID);
    // 8. gate_up
    gemm_atb<<<dim3(2 * II / 128, 16), 256>>>(ph2, wgu, nullptr, pgu, 2 * II, HID);
    // 9. act = silu(gate) * up
    silu_mul<<<(TT * II) / 256, 256>>>(pgu, pact);
    // 10. hidden += act @ w_down^T
    gemm_atb<<<dim3(16, 16), 256>>>(pact, wd, phid, phid, HID, II);
    // 11. out = hidden^T  ([T][HID] -> [HID][T])
    transpose_k<<<dim3(HID / 32, TT / 32), tb>>>(phid, out, TT, HID);
}

// round 3
// speedup vs baseline: 2.4228x; 2.4228x over previous
#include <cuda_runtime.h>
#include <cuda_bf16.h>
#include <cstdint>
#include <math.h>

// ---------------- problem constants ----------------
#define HH   16        // H
#define HKV  8
#define DD   128       // D
#define TT   2048      // T
#define HID  2048
#define II   8192      // I
#define NREP 2
#define EPSF 1e-6f
#define SCALEF 0.08838834764831845f   // 1/sqrt(128)

// ---------------- scratch (device globals, no allocs) ----------------
__device__ float g_x  [TT * HID];        // x  = hidden_conv^T
__device__ float g_h  [TT * HID];        // rms(x)
__device__ float g_q  [TT * HH  * DD];   // q  [T, H, D]
__device__ float g_k  [TT * HKV * DD];   // k  [T, HKV, D]
__device__ float g_v  [TT * HKV * DD];   // v
__device__ float g_att[TT * HH  * DD];   // attention out [T, H*D]
__device__ float g_hid[TT * HID];        // residual stream
__device__ float g_h2 [TT * HID];        // rms(hidden)
__device__ float g_gu [TT * 2 * II];     // gate_up output
__device__ float g_act[TT * II];         // silu(gate)*up

// ---------------- transpose: src[R][C] -> dst[C][R] ----------------
__global__ void transpose_k(const float* __restrict__ src, float* __restrict__ dst,
                            int R, int C) {
    __shared__ float tile[32][33];
    int r0 = blockIdx.y * 32, c0 = blockIdx.x * 32;
    int tx = threadIdx.x, ty = threadIdx.y;
    #pragma unroll
    for (int i = ty; i < 32; i += 8)
        tile[i][tx] = src[(size_t)(r0 + i) * C + c0 + tx];
    __syncthreads();
    #pragma unroll
    for (int i = ty; i < 32; i += 8)
        dst[(size_t)(c0 + i) * R + r0 + tx] = tile[tx][i];
}

// ---------------- row RMS norm ----------------
__global__ void rms_rows(const float* __restrict__ X, const float* __restrict__ w,
                         float* __restrict__ Y, int C) {
    int t = blockIdx.x;
    const float4* x4 = (const float4*)(X + (size_t)t * C);
    const float4* w4 = (const float4*)w;
    float4*       y4 = (float4*)(Y + (size_t)t * C);
    int n4 = C >> 2;
    float4 v[4];
    float ss = 0.f;
    int cnt = 0;
    for (int i = threadIdx.x; i < n4; i += 256) {
        float4 a = x4[i];
        v[cnt++] = a;
        ss += a.x * a.x + a.y * a.y + a.z * a.z + a.w * a.w;
    }
    #pragma unroll
    for (int o = 16; o; o >>= 1) ss += __shfl_xor_sync(0xffffffffu, ss, o);
    __shared__ float warpsum[8];
    if ((threadIdx.x & 31) == 0) warpsum[threadIdx.x >> 5] = ss;
    __syncthreads();
    ss = 0.f;
    #pragma unroll
    for (int i = 0; i < 8; i++) ss += warpsum[i];
    float r = rsqrtf(ss / (float)C + EPSF);
    cnt = 0;
    for (int i = threadIdx.x; i < n4; i += 256) {
        float4 a = v[cnt++];
        float4 ww = w4[i];
        float4 o;
        o.x = a.x * r * ww.x; o.y = a.y * r * ww.y;
        o.z = a.z * r * ww.z; o.w = a.w * r * ww.w;
        y4[i] = o;
    }
}

// ---------------- per-head RMS + RoPE (in place) ----------------
__global__ void qk_rms_rope(float* __restrict__ buf, const float* __restrict__ w,
                            const float* __restrict__ cosT, const float* __restrict__ sinT) {
    int h = blockIdx.x, t = blockIdx.y, nh = gridDim.x;
    float* row = buf + ((size_t)t * nh + h) * DD;
    int d = threadIdx.x;
    float v = row[d];
    float ss = v * v;
    #pragma unroll
    for (int o = 16; o; o >>= 1) ss += __shfl_xor_sync(0xffffffffu, ss, o);
    __shared__ float wsum[4];
    if ((d & 31) == 0) wsum[d >> 5] = ss;
    __syncthreads();
    ss = wsum[0] + wsum[1] + wsum[2] + wsum[3];
    float r = rsqrtf(ss / 128.f + EPSF);
    float qn = v * r * w[d];
    __shared__ float sh[128];
    sh[d] = qn;
    __syncthreads();
    float rot = (d < 64) ? -sh[d + 64] : sh[d - 64];
    row[d] = qn * cosT[(size_t)t * DD + d] + rot * sinT[(size_t)t * DD + d];
}

// ---------------- tf32 tensor-core GEMM: C[M,N] = A[M,K] * B[N,K]^T (+Res) ----
// 128x128x32 tile, 256 threads, 8 warps (2m x 4n), warp tile 64x32,
// mma.sync m16n8k8 tf32, double-buffered smem + register prefetch.
#define GPITCH 36
#define GABUF  (128 * GPITCH)
#define GEMM_SMEM (4 * GABUF * 4)   // 2 bufs x (A+B) x 4608 u32 = 73728 B

__device__ __forceinline__ uint32_t f2tf32(float f) {
    uint32_t o;
    asm("cvt.rna.tf32.f32 %0, %1;" : "=r"(o) : "f"(f));
    return o;
}

#define MMA_TF32(d, a, b)                                                     \
    asm volatile("mma.sync.aligned.m16n8k8.row.col.f32.tf32.tf32.f32 "        \
                 "{%0,%1,%2,%3}, {%4,%5,%6,%7}, {%8,%9}, {%0,%1,%2,%3};"      \
                 : "+f"(d[0]), "+f"(d[1]), "+f"(d[2]), "+f"(d[3])             \
                 : "r"(a[0]), "r"(a[1]), "r"(a[2]), "r"(a[3]),                \
                   "r"(b[0]), "r"(b[1]))

__global__ __launch_bounds__(256, 1) void gemm_tf32(
    const float* __restrict__ A, const float* __restrict__ B,
    const float* __restrict__ Res, float* __restrict__ C,
    int N, int K) {
    extern __shared__ uint32_t smu[];
    uint32_t* SA = smu;               // [2][128][36]
    uint32_t* SB = smu + 2 * GABUF;   // [2][128][36]

    const int bm = blockIdx.y * 128;
    const int bn = blockIdx.x * 128;
    const int tid = threadIdx.x;
    const int wid = tid >> 5, lane = tid & 31;
    const int wm = wid & 1, wn = wid >> 1;        // 2 x 4 warps
    const int lr = lane >> 2, lc = lane & 3;
    const int lrow = tid >> 3, lc4 = tid & 7;     // gmem tile loads

    float acc[4][4][4] = {};
    float4 pa[4], pb[4];

    const int nkt = K >> 5;

    // prologue: load k-tile 0
    #pragma unroll
    for (int t = 0; t < 4; t++) {
        int r = lrow + t * 32;
        pa[t] = *(const float4*)(A + (size_t)(bm + r) * K + lc4 * 4);
        pb[t] = *(const float4*)(B + (size_t)(bn + r) * K + lc4 * 4);
    }
    #pragma unroll
    for (int t = 0; t < 4; t++) {
        int r = lrow + t * 32;
        *(uint4*)&SA[r * GPITCH + lc4 * 4] =
            make_uint4(f2tf32(pa[t].x), f2tf32(pa[t].y), f2tf32(pa[t].z), f2tf32(pa[t].w));
        *(uint4*)&SB[r * GPITCH + lc4 * 4] =
            make_uint4(f2tf32(pb[t].x), f2tf32(pb[t].y), f2tf32(pb[t].z), f2tf32(pb[t].w));
    }
    __syncthreads();

    for (int kt = 0; kt < nkt; kt++) {
        int cur = kt & 1;
        // prefetch next k-tile into registers (overlaps with HMMA below)
        if (kt + 1 < nkt) {
            int k0 = (kt + 1) << 5;
            #pragma unroll
            for (int t = 0; t < 4; t++) {
                int r = lrow + t * 32;
                pa[t] = *(const float4*)(A + (size_t)(bm + r) * K + k0 + lc4 * 4);
                pb[t] = *(const float4*)(B + (size_t)(bn + r) * K + k0 + lc4 * 4);
            }
        }
        const uint32_t* Ab = SA + cur * GABUF;
        const uint32_t* Bb = SB + cur * GABUF;
        #pragma unroll
        for (int ks = 0; ks < 32; ks += 8) {
            uint32_t af[4][4], bf[4][2];
            #pragma unroll
            for (int mf = 0; mf < 4; mf++) {
                const uint32_t* p = Ab + (wm * 64 + mf * 16 + lr) * GPITCH + ks + lc;
                af[mf][0] = p[0];
                af[mf][1] = p[8 * GPITCH];
                af[mf][2] = p[4];
                af[mf][3] = p[8 * GPITCH + 4];
            }
            #pragma unroll
            for (int nf = 0; nf < 4; nf++) {
                const uint32_t* p = Bb + (wn * 32 + nf * 8 + lr) * GPITCH + ks + lc;
                bf[nf][0] = p[0];
                bf[nf][1] = p[4];
            }
            #pragma unroll
            for (int mf = 0; mf < 4; mf++)
                #pragma unroll
                for (int nf = 0; nf < 4; nf++)
                    MMA_TF32(acc[mf][nf], af[mf], bf[nf]);
        }
        if (kt + 1 < nkt) {
            __syncthreads();
            uint32_t* DA = SA + (cur ^ 1) * GABUF;
            uint32_t* DB = SB + (cur ^ 1) * GABUF;
            #pragma unroll
            for (int t = 0; t < 4; t++) {
                int r = lrow + t * 32;
                *(uint4*)&DA[r * GPITCH + lc4 * 4] =
                    make_uint4(f2tf32(pa[t].x), f2tf32(pa[t].y), f2tf32(pa[t].z), f2tf32(pa[t].w));
                *(uint4*)&DB[r * GPITCH + lc4 * 4] =
                    make_uint4(f2tf32(pb[t].x), f2tf32(pb[t].y), f2tf32(pb[t].z), f2tf32(pb[t].w));
            }
            __syncthreads();
        }
    }

    // epilogue
    #pragma unroll
    for (int mf = 0; mf < 4; mf++) {
        #pragma unroll
        for (int nf = 0; nf < 4; nf++) {
            int rg = bm + wm * 64 + mf * 16 + lr;
            int cg = bn + wn * 32 + nf * 8 + 2 * lc;
            float2 v0 = make_float2(acc[mf][nf][0], acc[mf][nf][1]);
            float2 v1 = make_float2(acc[mf][nf][2], acc[mf][nf][3]);
            if (Res) {
                float2 r0 = *(const float2*)(Res + (size_t)rg * N + cg);
                float2 r1 = *(const float2*)(Res + (size_t)(rg + 8) * N + cg);
                v0.x += r0.x; v0.y += r0.y;
                v1.x += r1.x; v1.y += r1.y;
            }
            *(float2*)(C + (size_t)rg * N + cg) = v0;
            *(float2*)(C + (size_t)(rg + 8) * N + cg) = v1;
        }
    }
}

// ---------------- flash attention (fp32, causal, 64x64 tiles) ----------------
#define FLASH_SMEM ((64*128 + 128*68 + 64*68) * 4)
__global__ __launch_bounds__(256) void flash_attn(
    const float* __restrict__ Q, const float* __restrict__ Kg,
    const float* __restrict__ Vg, float* __restrict__ O) {
    extern __shared__ float sm[];
    float* Qs = sm;                 // [64][128]
    float* KT = Qs + 64 * 128;      // K as [128][68] ; reused as V [64][132]
    float* Ss = KT + 128 * 68;      // [64][68]
    __shared__ float m_s[64], l_s[64], al_s[64];

    int h  = blockIdx.y;
    int it = blockIdx.x;
    int i0 = it * 64;
    int hk = h >> 1;                // NREP = 2
    int tid = threadIdx.x, tx = tid & 15, ty = tid >> 4;

    for (int idx = tid; idx < 64 * 32; idx += 256) {
        int r = idx >> 5, d4 = (idx & 31) << 2;
        float4 v = *(const float4*)(Q + ((size_t)(i0 + r) * HH + h) * DD + d4);
        v.x *= SCALEF; v.y *= SCALEF; v.z *= SCALEF; v.w *= SCALEF;
        *(float4*)&Qs[r * 128 + d4] = v;
    }
    if (tid < 64) { m_s[tid] = -1e30f; l_s[tid] = 0.f; }

    float acc[4][8] = {};

    for (int kt = 0; kt <= it; kt++) {
        int j0 = kt * 64;
        __syncthreads();
        for (int idx = tid; idx < 64 * 32; idx += 256) {
            int c = idx >> 5, d4 = (idx & 31) << 2;
            float4 v = *(const float4*)(Kg + ((size_t)(j0 + c) * HKV + hk) * DD + d4);
            KT[(d4 + 0) * 68 + c] = v.x;
            KT[(d4 + 1) * 68 + c] = v.y;
            KT[(d4 + 2) * 68 + c] = v.z;
            KT[(d4 + 3) * 68 + c] = v.w;
        }
        __syncthreads();
        float s[4][4] = {};
        #pragma unroll 4
        for (int d = 0; d < 128; d++) {
            float4 kv = *(const float4*)&KT[d * 68 + tx * 4];
            float q0 = Qs[(ty * 4 + 0) * 128 + d];
            float q1 = Qs[(ty * 4 + 1) * 128 + d];
            float q2 = Qs[(ty * 4 + 2) * 128 + d];
            float q3 = Qs[(ty * 4 + 3) * 128 + d];
            s[0][0] += q0 * kv.x; s[0][1] += q0 * kv.y; s[0][2] += q0 * kv.z; s[0][3] += q0 * kv.w;
            s[1][0] += q1 * kv.x; s[1][1] += q1 * kv.y; s[1][2] += q1 * kv.z; s[1][3] += q1 * kv.w;
            s[2][0] += q2 * kv.x; s[2][1] += q2 * kv.y; s[2][2] += q2 * kv.z; s[2][3] += q2 * kv.w;
            s[3][0] += q3 * kv.x; s[3][1] += q3 * kv.y; s[3][2] += q3 * kv.z; s[3][3] += q3 * kv.w;
        }
        bool diag = (kt == it);
        #pragma unroll
        for (int i = 0; i < 4; i++)
            #pragma unroll
            for (int j = 0; j < 4; j++) {
                float vv = s[i][j];
                if (diag && (tx * 4 + j > ty * 4 + i)) vv = -1e30f;
                Ss[(ty * 4 + i) * 68 + tx * 4 + j] = vv;
            }
        __syncthreads();
        for (int idx = tid; idx < 64 * 32; idx += 256) {
            int c = idx >> 5, d4 = (idx & 31) << 2;
            float4 v = *(const float4*)(Vg + ((size_t)(j0 + c) * HKV + hk) * DD + d4);
            *(float4*)&KT[c * 132 + d4] = v;
        }
        if (tid < 64) {
            int r = tid;
            float mo = m_s[r];
            float mx = mo;
            #pragma unroll 8
            for (int c = 0; c < 64; c++) mx = fmaxf(mx, Ss[r * 68 + c]);
            float al = __expf(mo - mx);
            float sum = 0.f;
            #pragma unroll 8
            for (int c = 0; c < 64; c++) {
                float p = __expf(Ss[r * 68 + c] - mx);
                Ss[r * 68 + c] = p;
                sum += p;
            }
            m_s[r] = mx;
            al_s[r] = al;
            l_s[r] = l_s[r] * al + sum;
        }
        __syncthreads();
        #pragma unroll
        for (int i = 0; i < 4; i++) {
            float a = al_s[ty * 4 + i];
            #pragma unroll
            for (int j = 0; j < 8; j++) acc[i][j] *= a;
        }
        #pragma unroll 2
        for (int c = 0; c < 64; c++) {
            float p0 = Ss[(ty * 4 + 0) * 68 + c];
            float p1 = Ss[(ty * 4 + 1) * 68 + c];
            float p2 = Ss[(ty * 4 + 2) * 68 + c];
            float p3 = Ss[(ty * 4 + 3) * 68 + c];
            float4 v0 = *(const float4*)&KT[c * 132 + tx * 8];
            float4 v1 = *(const float4*)&KT[c * 132 + tx * 8 + 4];
            acc[0][0] += p0 * v0.x; acc[0][1] += p0 * v0.y; acc[0][2] += p0 * v0.z; acc[0][3] += p0 * v0.w;
            acc[0][4] += p0 * v1.x; acc[0][5] += p0 * v1.y; acc[0][6] += p0 * v1.z; acc[0][7] += p0 * v1.w;
            acc[1][0] += p1 * v0.x; acc[1][1] += p1 * v0.y; acc[1][2] += p1 * v0.z; acc[1][3] += p1 * v0.w;
            acc[1][4] += p1 * v1.x; acc[1][5] += p1 * v1.y; acc[1][6] += p1 * v1.z; acc[1][7] += p1 * v1.w;
            acc[2][0] += p2 * v0.x; acc[2][1] += p2 * v0.y; acc[2][2] += p2 * v0.z; acc[2][3] += p2 * v0.w;
            acc[2][4] += p2 * v1.x; acc[2][5] += p2 * v1.y; acc[2][6] += p2 * v1.z; acc[2][7] += p2 * v1.w;
            acc[3][0] += p3 * v0.x; acc[3][1] += p3 * v0.y; acc[3][2] += p3 * v0.z; acc[3][3] += p3 * v0.w;
            acc[3][4] += p3 * v1.x; acc[3][5] += p3 * v1.y; acc[3][6] += p3 * v1.z; acc[3][7] += p3 * v1.w;
        }
    }
    #pragma unroll
    for (int i = 0; i < 4; i++) {
        int r = ty * 4 + i;
        float inv = 1.f / l_s[r];
        float* op = O + ((size_t)(i0 + r) * HH + h) * DD + tx * 8;
        float4 o0 = make_float4(acc[i][0] * inv, acc[i][1] * inv, acc[i][2] * inv, acc[i][3] * inv);
        float4 o1 = make_float4(acc[i][4] * inv, acc[i][5] * inv, acc[i][6] * inv, acc[i][7] * inv);
        *(float4*)(op)     = o0;
        *(float4*)(op + 4) = o1;
    }
}

// ---------------- silu(gate) * up ----------------
__global__ void silu_mul(const float* __restrict__ gu, float* __restrict__ act) {
    int idx = blockIdx.x * blockDim.x + threadIdx.x;   // over T*I
    int t = idx >> 13;
    int i = idx & 8191;
    float g = gu[(size_t)t * (2 * II) + i];
    float u = gu[(size_t)t * (2 * II) + II + i];
    act[idx] = g / (1.f + __expf(-g)) * u;
}

// ---------------- launch ----------------
extern "C" void kernel_launch(void* const* d_in, const int* in_sizes, int n_in,
                              void* d_out, int out_size) {
    const float* hc    = (const float*)d_in[0];
    const float* cosT  = (const float*)d_in[1];
    const float* sinT  = (const float*)d_in[2];
    const float* wq    = (const float*)d_in[5];
    const float* wk    = (const float*)d_in[6];
    const float* wv    = (const float*)d_in[7];
    const float* wo    = (const float*)d_in[8];
    const float* wgu   = (const float*)d_in[9];
    const float* wd    = (const float*)d_in[10];
    const float* ilnw  = (const float*)d_in[11];
    const float* plnw  = (const float*)d_in[12];
    const float* qnw   = (const float*)d_in[13];
    const float* knw   = (const float*)d_in[14];
    float* out = (float*)d_out;

    float *px, *ph, *pq, *pk, *pv, *patt, *phid, *ph2, *pgu, *pact;
    cudaGetSymbolAddress((void**)&px,   g_x);
    cudaGetSymbolAddress((void**)&ph,   g_h);
    cudaGetSymbolAddress((void**)&pq,   g_q);
    cudaGetSymbolAddress((void**)&pk,   g_k);
    cudaGetSymbolAddress((void**)&pv,   g_v);
    cudaGetSymbolAddress((void**)&patt, g_att);
    cudaGetSymbolAddress((void**)&phid, g_hid);
    cudaGetSymbolAddress((void**)&ph2,  g_h2);
    cudaGetSymbolAddress((void**)&pgu,  g_gu);
    cudaGetSymbolAddress((void**)&pact, g_act);

    cudaFuncSetAttribute(flash_attn, cudaFuncAttributeMaxDynamicSharedMemorySize, FLASH_SMEM);
    cudaFuncSetAttribute(gemm_tf32,  cudaFuncAttributeMaxDynamicSharedMemorySize, GEMM_SMEM);

    dim3 tb(32, 8);

    // 1. x = hidden_conv^T   (hc is [HID][T])
    transpose_k<<<dim3(TT / 32, HID / 32), tb>>>(hc, px, HID, TT);
    // 2. h = rms(x) * input_ln_w
    rms_rows<<<TT, 256>>>(px, ilnw, ph, HID);
    // 3. QKV projections (tf32 tensor cores)
    gemm_tf32<<<dim3(16, 16), 256, GEMM_SMEM>>>(ph, wq, nullptr, pq, HH * DD, HID);
    gemm_tf32<<<dim3(8, 16),  256, GEMM_SMEM>>>(ph, wk, nullptr, pk, HKV * DD, HID);
    gemm_tf32<<<dim3(8, 16),  256, GEMM_SMEM>>>(ph, wv, nullptr, pv, HKV * DD, HID);
    // 4. q/k head-RMS + rope (in place)
    qk_rms_rope<<<dim3(HH,  TT), 128>>>(pq, qnw, cosT, sinT);
    qk_rms_rope<<<dim3(HKV, TT), 128>>>(pk, knw, cosT, sinT);
    // 5. attention
    flash_attn<<<dim3(TT / 64, HH), 256, FLASH_SMEM>>>(pq, pk, pv, patt);
    // 6. hidden = x + att @ wo^T
    gemm_tf32<<<dim3(16, 16), 256, GEMM_SMEM>>>(patt, wo, px, phid, HID, HH * DD);
    // 7. h2 = rms(hidden) * post_ln_w
    rms_rows<<<TT, 256>>>(phid, plnw, ph2, HID);
    // 8. gate_up
    gemm_tf32<<<dim3(2 * II / 128, 16), 256, GEMM_SMEM>>>(ph2, wgu, nullptr, pgu, 2 * II, HID);
    // 9. act = silu(gate) * up
    silu_mul<<<(TT * II) / 256, 256>>>(pgu, pact);
    // 10. hidden += act @ w_down^T
    gemm_tf32<<<dim3(16, 16), 256, GEMM_SMEM>>>(pact, wd, phid, phid, HID, II);
    // 11. out = hidden^T  ([T][HID] -> [HID][T])
    transpose_k<<<dim3(HID / 32, TT / 32), tb>>>(phid, out, TT, HID);
}

// round 4
// speedup vs baseline: 2.5935x; 1.0704x over previous
#include <cuda_runtime.h>
#include <cuda_bf16.h>
#include <cstdint>
#include <math.h>

// ---------------- problem constants ----------------
#define HH   16        // H
#define HKV  8
#define DD   128       // D
#define TT   2048      // T
#define HID  2048
#define II   8192      // I
#define NREP 2
#define EPSF 1e-6f
#define SCALEF 0.08838834764831845f   // 1/sqrt(128)

// ---------------- scratch (device globals, no allocs) ----------------
__device__ float g_x  [TT * HID];
__device__ float g_h  [TT * HID];
__device__ float g_q  [TT * HH  * DD];
__device__ float g_k  [TT * HKV * DD];
__device__ float g_v  [TT * HKV * DD];
__device__ float g_att[TT * HH  * DD];
__device__ float g_hid[TT * HID];
__device__ float g_h2 [TT * HID];
__device__ float g_gu [TT * 2 * II];
__device__ float g_act[TT * II];

// ---------------- transpose: src[R][C] -> dst[C][R] ----------------
__global__ void transpose_k(const float* __restrict__ src, float* __restrict__ dst,
                            int R, int C) {
    __shared__ float tile[32][33];
    int r0 = blockIdx.y * 32, c0 = blockIdx.x * 32;
    int tx = threadIdx.x, ty = threadIdx.y;
    #pragma unroll
    for (int i = ty; i < 32; i += 8)
        tile[i][tx] = src[(size_t)(r0 + i) * C + c0 + tx];
    __syncthreads();
    #pragma unroll
    for (int i = ty; i < 32; i += 8)
        dst[(size_t)(c0 + i) * R + r0 + tx] = tile[tx][i];
}

// ---------------- row RMS norm ----------------
__global__ void rms_rows(const float* __restrict__ X, const float* __restrict__ w,
                         float* __restrict__ Y, int C) {
    int t = blockIdx.x;
    const float4* x4 = (const float4*)(X + (size_t)t * C);
    const float4* w4 = (const float4*)w;
    float4*       y4 = (float4*)(Y + (size_t)t * C);
    int n4 = C >> 2;
    float4 v[4];
    float ss = 0.f;
    int cnt = 0;
    for (int i = threadIdx.x; i < n4; i += 256) {
        float4 a = x4[i];
        v[cnt++] = a;
        ss += a.x * a.x + a.y * a.y + a.z * a.z + a.w * a.w;
    }
    #pragma unroll
    for (int o = 16; o; o >>= 1) ss += __shfl_xor_sync(0xffffffffu, ss, o);
    __shared__ float warpsum[8];
    if ((threadIdx.x & 31) == 0) warpsum[threadIdx.x >> 5] = ss;
    __syncthreads();
    ss = 0.f;
    #pragma unroll
    for (int i = 0; i < 8; i++) ss += warpsum[i];
    float r = rsqrtf(ss / (float)C + EPSF);
    cnt = 0;
    for (int i = threadIdx.x; i < n4; i += 256) {
        float4 a = v[cnt++];
        float4 ww = w4[i];
        float4 o;
        o.x = a.x * r * ww.x; o.y = a.y * r * ww.y;
        o.z = a.z * r * ww.z; o.w = a.w * r * ww.w;
        y4[i] = o;
    }
}

// ---------------- per-head RMS + RoPE (in place) ----------------
__global__ void qk_rms_rope(float* __restrict__ buf, const float* __restrict__ w,
                            const float* __restrict__ cosT, const float* __restrict__ sinT) {
    int h = blockIdx.x, t = blockIdx.y, nh = gridDim.x;
    float* row = buf + ((size_t)t * nh + h) * DD;
    int d = threadIdx.x;
    float v = row[d];
    float ss = v * v;
    #pragma unroll
    for (int o = 16; o; o >>= 1) ss += __shfl_xor_sync(0xffffffffu, ss, o);
    __shared__ float wsum[4];
    if ((d & 31) == 0) wsum[d >> 5] = ss;
    __syncthreads();
    ss = wsum[0] + wsum[1] + wsum[2] + wsum[3];
    float r = rsqrtf(ss / 128.f + EPSF);
    float qn = v * r * w[d];
    __shared__ float sh[128];
    sh[d] = qn;
    __syncthreads();
    float rot = (d < 64) ? -sh[d + 64] : sh[d - 64];
    row[d] = qn * cosT[(size_t)t * DD + d] + rot * sinT[(size_t)t * DD + d];
}

// ---------------- tf32 tensor-core GEMM with cp.async 3-stage pipeline -------
// C[M,N] = A[M,K] * B[N,K]^T (+Res).  BM=128, BN template {128,256},
// 256 threads, 8 warps (2m x 4n), warp tile 64 x (BN/4), mma m16n8k8 tf32.
// fp32 kept in smem; cvt to tf32 at fragment-load time.
#define GPITCH 36

__device__ __forceinline__ uint32_t f2tf32(float f) {
    uint32_t o;
    asm("cvt.rna.tf32.f32 %0, %1;" : "=r"(o) : "f"(f));
    return o;
}

#define MMA_TF32(d, a, b)                                                     \
    asm volatile("mma.sync.aligned.m16n8k8.row.col.f32.tf32.tf32.f32 "        \
                 "{%0,%1,%2,%3}, {%4,%5,%6,%7}, {%8,%9}, {%0,%1,%2,%3};"      \
                 : "+f"(d[0]), "+f"(d[1]), "+f"(d[2]), "+f"(d[3])             \
                 : "r"(a[0]), "r"(a[1]), "r"(a[2]), "r"(a[3]),                \
                   "r"(b[0]), "r"(b[1]))

template<int BN, int MINB>
__global__ __launch_bounds__(256, MINB) void gemm_tf32_ca(
    const float* __restrict__ A, const float* __restrict__ B,
    const float* __restrict__ Res, float* __restrict__ C,
    int N, int K) {
    constexpr int BM   = 128;
    constexpr int NSTG = 3;
    constexpr int WN   = BN / 4;     // warp n-tile
    constexpr int NF   = WN / 8;     // b-fragments per warp
    extern __shared__ float smf[];
    float* SA = smf;                          // [NSTG][BM][GPITCH]
    float* SB = smf + NSTG * BM * GPITCH;     // [NSTG][BN][GPITCH]

    const int bm = blockIdx.y * BM;
    const int bn = blockIdx.x * BN;
    const int tid = threadIdx.x;
    const int wid = tid >> 5, lane = tid & 31;
    const int wm = wid & 1, wn = wid >> 1;
    const int lr = lane >> 2, lc = lane & 3;
    const int nkt = K >> 5;

    // cp.async one 32-wide k-stage into buffer s
    auto issue = [&](int kt, int s) {
        int k0 = kt << 5;
        #pragma unroll
        for (int i = 0; i < BM / 32; i++) {
            int c = tid + i * 256;
            int r = c >> 3, c4 = (c & 7) << 2;
            const float* g = A + (size_t)(bm + r) * K + k0 + c4;
            uint32_t dst = (uint32_t)__cvta_generic_to_shared(
                &SA[(s * BM + r) * GPITCH + c4]);
            asm volatile("cp.async.cg.shared.global [%0], [%1], 16;\n"
                         :: "r"(dst), "l"(g));
        }
        #pragma unroll
        for (int i = 0; i < BN / 32; i++) {
            int c = tid + i * 256;
            int r = c >> 3, c4 = (c & 7) << 2;
            const float* g = B + (size_t)(bn + r) * K + k0 + c4;
            uint32_t dst = (uint32_t)__cvta_generic_to_shared(
                &SB[(s * BN + r) * GPITCH + c4]);
            asm volatile("cp.async.cg.shared.global [%0], [%1], 16;\n"
                         :: "r"(dst), "l"(g));
        }
        asm volatile("cp.async.commit_group;\n");
    };

    float acc[4][NF][4] = {};

    issue(0, 0);
    issue(1, 1);

    for (int kt = 0; kt < nkt; kt++) {
        int s = kt % 3;
        if (kt == nkt - 1) { asm volatile("cp.async.wait_group 0;\n"); }
        else               { asm volatile("cp.async.wait_group 1;\n"); }
        __syncthreads();
        // stage kt resident; buffer (kt+2)%3 (= stage kt-1's) is free now
        if (kt + 2 < nkt) issue(kt + 2, (kt + 2) % 3);

        const float* Ab = SA + (size_t)s * BM * GPITCH;
        const float* Bb = SB + (size_t)s * BN * GPITCH;
        #pragma unroll
        for (int ks = 0; ks < 32; ks += 8) {
            uint32_t af[4][4], bf[NF][2];
            #pragma unroll
            for (int mf = 0; mf < 4; mf++) {
                const float* p = Ab + (wm * 64 + mf * 16 + lr) * GPITCH + ks + lc;
                af[mf][0] = f2tf32(p[0]);
                af[mf][1] = f2tf32(p[8 * GPITCH]);
                af[mf][2] = f2tf32(p[4]);
                af[mf][3] = f2tf32(p[8 * GPITCH + 4]);
            }
            #pragma unroll
            for (int nf = 0; nf < NF; nf++) {
                const float* p = Bb + (wn * WN + nf * 8 + lr) * GPITCH + ks + lc;
                bf[nf][0] = f2tf32(p[0]);
                bf[nf][1] = f2tf32(p[4]);
            }
            #pragma unroll
            for (int mf = 0; mf < 4; mf++)
                #pragma unroll
                for (int nf = 0; nf < NF; nf++)
                    MMA_TF32(acc[mf][nf], af[mf], bf[nf]);
        }
    }

    // epilogue
    #pragma unroll
    for (int mf = 0; mf < 4; mf++) {
        #pragma unroll
        for (int nf = 0; nf < NF; nf++) {
            int rg = bm + wm * 64 + mf * 16 + lr;
            int cg = bn + wn * WN + nf * 8 + 2 * lc;
            float2 v0 = make_float2(acc[mf][nf][0], acc[mf][nf][1]);
            float2 v1 = make_float2(acc[mf][nf][2], acc[mf][nf][3]);
            if (Res) {
                float2 r0 = *(const float2*)(Res + (size_t)rg * N + cg);
                float2 r1 = *(const float2*)(Res + (size_t)(rg + 8) * N + cg);
                v0.x += r0.x; v0.y += r0.y;
                v1.x += r1.x; v1.y += r1.y;
            }
            *(float2*)(C + (size_t)rg * N + cg) = v0;
            *(float2*)(C + (size_t)(rg + 8) * N + cg) = v1;
        }
    }
}

#define SMEM_G128 (3 * (128 + 128) * GPITCH * 4)   // 110592 B
#define SMEM_G256 (3 * (128 + 256) * GPITCH * 4)   // 165888 B

// ---------------- flash attention (fp32, causal, 64x64 tiles) ----------------
#define FLASH_SMEM ((64*128 + 128*68 + 64*68) * 4)
__global__ __launch_bounds__(256) void flash_attn(
    const float* __restrict__ Q, const float* __restrict__ Kg,
    const float* __restrict__ Vg, float* __restrict__ O) {
    extern __shared__ float sm[];
    float* Qs = sm;                 // [64][128]
    float* KT = Qs + 64 * 128;      // K as [128][68] ; reused as V [64][132]
    float* Ss = KT + 128 * 68;      // [64][68]
    __shared__ float m_s[64], l_s[64], al_s[64];

    int h  = blockIdx.y;
    int it = blockIdx.x;
    int i0 = it * 64;
    int hk = h >> 1;                // NREP = 2
    int tid = threadIdx.x, tx = tid & 15, ty = tid >> 4;

    for (int idx = tid; idx < 64 * 32; idx += 256) {
        int r = idx >> 5, d4 = (idx & 31) << 2;
        float4 v = *(const float4*)(Q + ((size_t)(i0 + r) * HH + h) * DD + d4);
        v.x *= SCALEF; v.y *= SCALEF; v.z *= SCALEF; v.w *= SCALEF;
        *(float4*)&Qs[r * 128 + d4] = v;
    }
    if (tid < 64) { m_s[tid] = -1e30f; l_s[tid] = 0.f; }

    float acc[4][8] = {};

    for (int kt = 0; kt <= it; kt++) {
        int j0 = kt * 64;
        __syncthreads();
        for (int idx = tid; idx < 64 * 32; idx += 256) {
            int c = idx >> 5, d4 = (idx & 31) << 2;
            float4 v = *(const float4*)(Kg + ((size_t)(j0 + c) * HKV + hk) * DD + d4);
            KT[(d4 + 0) * 68 + c] = v.x;
            KT[(d4 + 1) * 68 + c] = v.y;
            KT[(d4 + 2) * 68 + c] = v.z;
            KT[(d4 + 3) * 68 + c] = v.w;
        }
        __syncthreads();
        float s[4][4] = {};
        #pragma unroll 4
        for (int d = 0; d < 128; d++) {
            float4 kv = *(const float4*)&KT[d * 68 + tx * 4];
            float q0 = Qs[(ty * 4 + 0) * 128 + d];
            float q1 = Qs[(ty * 4 + 1) * 128 + d];
            float q2 = Qs[(ty * 4 + 2) * 128 + d];
            float q3 = Qs[(ty * 4 + 3) * 128 + d];
            s[0][0] += q0 * kv.x; s[0][1] += q0 * kv.y; s[0][2] += q0 * kv.z; s[0][3] += q0 * kv.w;
            s[1][0] += q1 * kv.x; s[1][1] += q1 * kv.y; s[1][2] += q1 * kv.z; s[1][3] += q1 * kv.w;
            s[2][0] += q2 * kv.x; s[2][1] += q2 * kv.y; s[2][2] += q2 * kv.z; s[2][3] += q2 * kv.w;
            s[3][0] += q3 * kv.x; s[3][1] += q3 * kv.y; s[3][2] += q3 * kv.z; s[3][3] += q3 * kv.w;
        }
        bool diag = (kt == it);
        #pragma unroll
        for (int i = 0; i < 4; i++)
            #pragma unroll
            for (int j = 0; j < 4; j++) {
                float vv = s[i][j];
                if (diag && (tx * 4 + j > ty * 4 + i)) vv = -1e30f;
                Ss[(ty * 4 + i) * 68 + tx * 4 + j] = vv;
            }
        __syncthreads();
        for (int idx = tid; idx < 64 * 32; idx += 256) {
            int c = idx >> 5, d4 = (idx & 31) << 2;
            float4 v = *(const float4*)(Vg + ((size_t)(j0 + c) * HKV + hk) * DD + d4);
            *(float4*)&KT[c * 132 + d4] = v;
        }
        if (tid < 64) {
            int r = tid;
            float mo = m_s[r];
            float mx = mo;
            #pragma unroll 8
            for (int c = 0; c < 64; c++) mx = fmaxf(mx, Ss[r * 68 + c]);
            float al = __expf(mo - mx);
            float sum = 0.f;
            #pragma unroll 8
            for (int c = 0; c < 64; c++) {
                float p = __expf(Ss[r * 68 + c] - mx);
                Ss[r * 68 + c] = p;
                sum += p;
            }
            m_s[r] = mx;
            al_s[r] = al;
            l_s[r] = l_s[r] * al + sum;
        }
        __syncthreads();
        #pragma unroll
        for (int i = 0; i < 4; i++) {
            float a = al_s[ty * 4 + i];
            #pragma unroll
            for (int j = 0; j < 8; j++) acc[i][j] *= a;
        }
        #pragma unroll 2
        for (int c = 0; c < 64; c++) {
            float p0 = Ss[(ty * 4 + 0) * 68 + c];
            float p1 = Ss[(ty * 4 + 1) * 68 + c];
            float p2 = Ss[(ty * 4 + 2) * 68 + c];
            float p3 = Ss[(ty * 4 + 3) * 68 + c];
            float4 v0 = *(const float4*)&KT[c * 132 + tx * 8];
            float4 v1 = *(const float4*)&KT[c * 132 + tx * 8 + 4];
            acc[0][0] += p0 * v0.x; acc[0][1] += p0 * v0.y; acc[0][2] += p0 * v0.z; acc[0][3] += p0 * v0.w;
            acc[0][4] += p0 * v1.x; acc[0][5] += p0 * v1.y; acc[0][6] += p0 * v1.z; acc[0][7] += p0 * v1.w;
            acc[1][0] += p1 * v0.x; acc[1][1] += p1 * v0.y; acc[1][2] += p1 * v0.z; acc[1][3] += p1 * v0.w;
            acc[1][4] += p1 * v1.x; acc[1][5] += p1 * v1.y; acc[1][6] += p1 * v1.z; acc[1][7] += p1 * v1.w;
            acc[2][0] += p2 * v0.x; acc[2][1] += p2 * v0.y; acc[2][2] += p2 * v0.z; acc[2][3] += p2 * v0.w;
            acc[2][4] += p2 * v1.x; acc[2][5] += p2 * v1.y; acc[2][6] += p2 * v1.z; acc[2][7] += p2 * v1.w;
            acc[3][0] += p3 * v0.x; acc[3][1] += p3 * v0.y; acc[3][2] += p3 * v0.z; acc[3][3] += p3 * v0.w;
            acc[3][4] += p3 * v1.x; acc[3][5] += p3 * v1.y; acc[3][6] += p3 * v1.z; acc[3][7] += p3 * v1.w;
        }
    }
    #pragma unroll
    for (int i = 0; i < 4; i++) {
        int r = ty * 4 + i;
        float inv = 1.f / l_s[r];
        float* op = O + ((size_t)(i0 + r) * HH + h) * DD + tx * 8;
        float4 o0 = make_float4(acc[i][0] * inv, acc[i][1] * inv, acc[i][2] * inv, acc[i][3] * inv);
        float4 o1 = make_float4(acc[i][4] * inv, acc[i][5] * inv, acc[i][6] * inv, acc[i][7] * inv);
        *(float4*)(op)     = o0;
        *(float4*)(op + 4) = o1;
    }
}

// ---------------- silu(gate) * up ----------------
__global__ void silu_mul(const float* __restrict__ gu, float* __restrict__ act) {
    int idx = blockIdx.x * blockDim.x + threadIdx.x;   // over T*I
    int t = idx >> 13;
    int i = idx & 8191;
    float g = gu[(size_t)t * (2 * II) + i];
    float u = gu[(size_t)t * (2 * II) + II + i];
    act[idx] = g / (1.f + __expf(-g)) * u;
}

// ---------------- launch ----------------
extern "C" void kernel_launch(void* const* d_in, const int* in_sizes, int n_in,
                              void* d_out, int out_size) {
    const float* hc    = (const float*)d_in[0];
    const float* cosT  = (const float*)d_in[1];
    const float* sinT  = (const float*)d_in[2];
    const float* wq    = (const float*)d_in[5];
    const float* wk    = (const float*)d_in[6];
    const float* wv    = (const float*)d_in[7];
    const float* wo    = (const float*)d_in[8];
    const float* wgu   = (const float*)d_in[9];
    const float* wd    = (const float*)d_in[10];
    const float* ilnw  = (const float*)d_in[11];
    const float* plnw  = (const float*)d_in[12];
    const float* qnw   = (const float*)d_in[13];
    const float* knw   = (const float*)d_in[14];
    float* out = (float*)d_out;

    float *px, *ph, *pq, *pk, *pv, *patt, *phid, *ph2, *pgu, *pact;
    cudaGetSymbolAddress((void**)&px,   g_x);
    cudaGetSymbolAddress((void**)&ph,   g_h);
    cudaGetSymbolAddress((void**)&pq,   g_q);
    cudaGetSymbolAddress((void**)&pk,   g_k);
    cudaGetSymbolAddress((void**)&pv,   g_v);
    cudaGetSymbolAddress((void**)&patt, g_att);
    cudaGetSymbolAddress((void**)&phid, g_hid);
    cudaGetSymbolAddress((void**)&ph2,  g_h2);
    cudaGetSymbolAddress((void**)&pgu,  g_gu);
    cudaGetSymbolAddress((void**)&pact, g_act);

    cudaFuncSetAttribute(flash_attn, cudaFuncAttributeMaxDynamicSharedMemorySize, FLASH_SMEM);
    cudaFuncSetAttribute(gemm_tf32_ca<128, 2>, cudaFuncAttributeMaxDynamicSharedMemorySize, SMEM_G128);
    cudaFuncSetAttribute(gemm_tf32_ca<256, 1>, cudaFuncAttributeMaxDynamicSharedMemorySize, SMEM_G256);

    dim3 tb(32, 8);

    // 1. x = hidden_conv^T   (hc is [HID][T])
    transpose_k<<<dim3(TT / 32, HID / 32), tb>>>(hc, px, HID, TT);
    // 2. h = rms(x) * input_ln_w
    rms_rows<<<TT, 256>>>(px, ilnw, ph, HID);
    // 3. QKV projections (tf32 tensor cores, cp.async pipeline)
    gemm_tf32_ca<256, 1><<<dim3(8, 16), 256, SMEM_G256>>>(ph, wq, nullptr, pq, HH * DD, HID);
    gemm_tf32_ca<128, 2><<<dim3(8, 16), 256, SMEM_G128>>>(ph, wk, nullptr, pk, HKV * DD, HID);
    gemm_tf32_ca<128, 2><<<dim3(8, 16), 256, SMEM_G128>>>(ph, wv, nullptr, pv, HKV * DD, HID);
    // 4. q/k head-RMS + rope (in place)
    qk_rms_rope<<<dim3(HH,  TT), 128>>>(pq, qnw, cosT, sinT);
    qk_rms_rope<<<dim3(HKV, TT), 128>>>(pk, knw, cosT, sinT);
    // 5. attention
    flash_attn<<<dim3(TT / 64, HH), 256, FLASH_SMEM>>>(pq, pk, pv, patt);
    // 6. hidden = x + att @ wo^T
    gemm_tf32_ca<256, 1><<<dim3(8, 16), 256, SMEM_G256>>>(patt, wo, px, phid, HID, HH * DD);
    // 7. h2 = rms(hidden) * post_ln_w
    rms_rows<<<TT, 256>>>(phid, plnw, ph2, HID);
    // 8. gate_up
    gemm_tf32_ca<256, 1><<<dim3(2 * II / 256, 16), 256, SMEM_G256>>>(ph2, wgu, nullptr, pgu, 2 * II, HID);
    // 9. act = silu(gate) * up
    silu_mul<<<(TT * II) / 256, 256>>>(pgu, pact);
    // 10. hidden += act @ w_down^T
    gemm_tf32_ca<256, 1><<<dim3(8, 16), 256, SMEM_G256>>>(pact, wd, phid, phid, HID, II);
    // 11. out = hidden^T  ([T][HID] -> [HID][T])
    transpose_k<<<dim3(HID / 32, TT / 32), tb>>>(phid, out, TT, HID);
}